// round 1
// baseline (speedup 1.0000x reference)
#include <cuda_runtime.h>
#include <math.h>

#define NMAX 100000
#define EMAX 1600000
#define INFT 128
#define OUTF 64

// Scratch (device globals: allocation-free per harness rules)
__device__ float g_h[NMAX * OUTF];      // h = x @ W
__device__ float g_hp[NMAX * OUTF];     // weighted scatter accumulator
__device__ float g_s1[NMAX];
__device__ float g_s2[NMAX];
__device__ float g_rowsum[NMAX];

// ---------------------------------------------------------------------------
// Kernel 1: h = x @ W   (x: [n,128] f32, W: [128,64] f32, h: [n,64] f32)
// Block: 256 threads, tile = 128 rows x 64 cols, thread = 8 rows x 4 cols.
// ---------------------------------------------------------------------------
__global__ __launch_bounds__(256) void k_gemm(const float* __restrict__ x,
                                              const float* __restrict__ W,
                                              int n) {
    __shared__ float Ws[INFT * OUTF];   // 32 KB
    __shared__ float xs[128 * 17];      // 128 rows x 16 k, pad 17 to dodge conflicts

    const int tid = threadIdx.x;

    // Load all of W into smem (8192 floats)
    for (int i = tid * 4; i < INFT * OUTF; i += 256 * 4) {
        *(float4*)&Ws[i] = *(const float4*)&W[i];
    }

    const int row0 = blockIdx.x * 128;
    const int cg = tid & 15;            // 16 col-groups of 4
    const int rg = tid >> 4;            // 16 row-groups of 8
    const int c0 = cg * 4;
    const int r0 = rg * 8;

    float acc[8][4];
#pragma unroll
    for (int i = 0; i < 8; i++)
#pragma unroll
        for (int j = 0; j < 4; j++) acc[i][j] = 0.f;

    for (int kc = 0; kc < INFT; kc += 16) {
        __syncthreads();
        // Cooperative load of 128x16 x-tile (2 float4 per thread)
        const int idx0 = tid * 8;
#pragma unroll
        for (int j = 0; j < 8; j += 4) {
            int idx = idx0 + j;
            int r = idx >> 4;
            int k = idx & 15;
            float4 v = make_float4(0.f, 0.f, 0.f, 0.f);
            if (row0 + r < n) {
                v = *(const float4*)&x[(row0 + r) * INFT + kc + k];
            }
            xs[r * 17 + k + 0] = v.x;
            xs[r * 17 + k + 1] = v.y;
            xs[r * 17 + k + 2] = v.z;
            xs[r * 17 + k + 3] = v.w;
        }
        __syncthreads();

#pragma unroll
        for (int k = 0; k < 16; k++) {
            float4 w4 = *(const float4*)&Ws[(kc + k) * OUTF + c0];
#pragma unroll
            for (int i = 0; i < 8; i++) {
                float xv = xs[(r0 + i) * 17 + k];
                acc[i][0] += xv * w4.x;
                acc[i][1] += xv * w4.y;
                acc[i][2] += xv * w4.z;
                acc[i][3] += xv * w4.w;
            }
        }
    }

#pragma unroll
    for (int i = 0; i < 8; i++) {
        int r = row0 + r0 + i;
        if (r < n) {
            float4 o = make_float4(acc[i][0], acc[i][1], acc[i][2], acc[i][3]);
            *(float4*)&g_h[r * OUTF + c0] = o;
        }
    }
}

// ---------------------------------------------------------------------------
// Kernel 2: per-node s1 = h[i].a1, s2 = h[i].a2; zero hp row + rowsum.
// ---------------------------------------------------------------------------
__global__ __launch_bounds__(256) void k_prep(const float* __restrict__ a, int n) {
    __shared__ float as[2 * OUTF];
    if (threadIdx.x < 2 * OUTF) as[threadIdx.x] = a[threadIdx.x];
    __syncthreads();

    int i = blockIdx.x * blockDim.x + threadIdx.x;
    if (i >= n) return;

    const float4* hr = (const float4*)&g_h[i * OUTF];
    float4* hpr = (float4*)&g_hp[i * OUTF];
    float s1 = 0.f, s2 = 0.f;
#pragma unroll
    for (int q = 0; q < 16; q++) {
        float4 v = hr[q];
        s1 += v.x * as[q * 4 + 0] + v.y * as[q * 4 + 1] +
              v.z * as[q * 4 + 2] + v.w * as[q * 4 + 3];
        s2 += v.x * as[OUTF + q * 4 + 0] + v.y * as[OUTF + q * 4 + 1] +
              v.z * as[OUTF + q * 4 + 2] + v.w * as[OUTF + q * 4 + 3];
        hpr[q] = make_float4(0.f, 0.f, 0.f, 0.f);
    }
    g_s1[i] = s1;
    g_s2[i] = s2;
    g_rowsum[i] = 0.f;
}

// ---------------------------------------------------------------------------
// Kernel 3: edge scatter. One warp handles 32 edges.
// Step A: lane e computes w_e = exp(-leaky_relu(s1[src]+s2[dst])) and
//         accumulates rowsum[src].
// Step B: 32 broadcast rounds; whole warp does coalesced 256B load of h[dst]
//         and coalesced atomicAdd scatter into hp[src] (2 cols / lane).
// ---------------------------------------------------------------------------
__global__ __launch_bounds__(256) void k_edge(const int* __restrict__ edge,
                                              int e_total) {
    const int lane = threadIdx.x & 31;
    const int warp = (blockIdx.x * blockDim.x + threadIdx.x) >> 5;
    const int base = warp * 32;
    if (base >= e_total) return;

    int e = base + lane;
    int src = 0, dst = 0;
    float w = 0.f;
    if (e < e_total) {
        src = edge[e];
        dst = edge[e_total + e];
        float sc = g_s1[src] + g_s2[dst];
        float lr = sc > 0.f ? sc : 0.2f * sc;
        w = expf(-lr);
        atomicAdd(&g_rowsum[src], w);
    }

    const int cnt = min(32, e_total - base);
    const int c = lane * 2;
    for (int j = 0; j < cnt; j++) {
        int s = __shfl_sync(0xffffffffu, src, j);
        int d = __shfl_sync(0xffffffffu, dst, j);
        float wj = __shfl_sync(0xffffffffu, w, j);
        float2 hv = *(const float2*)&g_h[d * OUTF + c];
        atomicAdd(&g_hp[s * OUTF + c + 0], wj * hv.x);
        atomicAdd(&g_hp[s * OUTF + c + 1], wj * hv.y);
    }
}

// ---------------------------------------------------------------------------
// Kernel 4: out = elu(hp / rowsum)
// ---------------------------------------------------------------------------
__device__ __forceinline__ float elu1(float v) {
    return v > 0.f ? v : expm1f(v);
}

__global__ __launch_bounds__(256) void k_final(float* __restrict__ out, int n) {
    int t = blockIdx.x * blockDim.x + threadIdx.x;
    if (t >= n * 16) return;
    int node = t >> 4;
    int q = t & 15;
    float r = g_rowsum[node];
    float4 v = *(const float4*)&g_hp[node * OUTF + q * 4];
    float4 o;
    o.x = elu1(v.x / r);
    o.y = elu1(v.y / r);
    o.z = elu1(v.z / r);
    o.w = elu1(v.w / r);
    *(float4*)&out[node * OUTF + q * 4] = o;
}

// ---------------------------------------------------------------------------
extern "C" void kernel_launch(void* const* d_in, const int* in_sizes, int n_in,
                              void* d_out, int out_size) {
    const float* x = (const float*)d_in[0];     // [n, 128]
    const float* W = (const float*)d_in[1];     // [128, 64]
    const float* a = (const float*)d_in[2];     // [1, 128]
    const int* edge = (const int*)d_in[3];      // [2, E]
    float* out = (float*)d_out;                 // [n, 64]

    const int n = in_sizes[0] / INFT;
    const int e = in_sizes[3] / 2;

    k_gemm<<<(n + 127) / 128, 256>>>(x, W, n);
    k_prep<<<(n + 255) / 256, 256>>>(a, n);
    // 8 warps/block, 32 edges/warp -> 256 edges per block
    k_edge<<<(e + 255) / 256, 256>>>(edge, e);
    k_final<<<(n * 16 + 255) / 256, 256>>>(out, n);
}

// round 2
// speedup vs baseline: 1.3337x; 1.3337x over previous
#include <cuda_runtime.h>
#include <math.h>

#define NMAX 100000
#define EMAX 1600000
#define INFT 128
#define OUTF 64

// Scratch (device globals: allocation-free per harness rules)
__device__ float g_h[NMAX * OUTF];      // h = x @ W
__device__ float g_hp[NMAX * OUTF];     // weighted scatter accumulator
__device__ float g_s1[NMAX];
__device__ float g_s2[NMAX];
__device__ float g_rowsum[NMAX];

__device__ __forceinline__ void red_add_v4(float* addr, float a, float b,
                                           float c, float d) {
    asm volatile("red.global.add.v4.f32 [%0], {%1,%2,%3,%4};"
                 :: "l"(addr), "f"(a), "f"(b), "f"(c), "f"(d) : "memory");
}

// ---------------------------------------------------------------------------
// Kernel 1: h = x @ W, fused with s1/s2 epilogue + hp/rowsum zeroing.
// Block: 256 threads, tile = 128 rows x 64 cols, thread = 8 rows x 4 cols.
// ---------------------------------------------------------------------------
__global__ __launch_bounds__(256) void k_gemm(const float* __restrict__ x,
                                              const float* __restrict__ W,
                                              const float* __restrict__ a,
                                              int n) {
    __shared__ float Ws[INFT * OUTF];   // 32 KB
    __shared__ float xs[128 * 17];      // 128 rows x 16 k, pad to dodge conflicts

    const int tid = threadIdx.x;

    for (int i = tid * 4; i < INFT * OUTF; i += 256 * 4) {
        *(float4*)&Ws[i] = *(const float4*)&W[i];
    }

    const int row0 = blockIdx.x * 128;
    const int cg = tid & 15;            // 16 col-groups of 4
    const int rg = tid >> 4;            // 16 row-groups of 8
    const int c0 = cg * 4;
    const int r0 = rg * 8;

    float acc[8][4];
#pragma unroll
    for (int i = 0; i < 8; i++)
#pragma unroll
        for (int j = 0; j < 4; j++) acc[i][j] = 0.f;

    for (int kc = 0; kc < INFT; kc += 16) {
        __syncthreads();
        const int idx0 = tid * 8;
#pragma unroll
        for (int j = 0; j < 8; j += 4) {
            int idx = idx0 + j;
            int r = idx >> 4;
            int k = idx & 15;
            float4 v = make_float4(0.f, 0.f, 0.f, 0.f);
            if (row0 + r < n) {
                v = *(const float4*)&x[(row0 + r) * INFT + kc + k];
            }
            xs[r * 17 + k + 0] = v.x;
            xs[r * 17 + k + 1] = v.y;
            xs[r * 17 + k + 2] = v.z;
            xs[r * 17 + k + 3] = v.w;
        }
        __syncthreads();

#pragma unroll
        for (int k = 0; k < 16; k++) {
            float4 w4 = *(const float4*)&Ws[(kc + k) * OUTF + c0];
#pragma unroll
            for (int i = 0; i < 8; i++) {
                float xv = xs[(r0 + i) * 17 + k];
                acc[i][0] += xv * w4.x;
                acc[i][1] += xv * w4.y;
                acc[i][2] += xv * w4.z;
                acc[i][3] += xv * w4.w;
            }
        }
    }

    // Epilogue: store h, zero hp, compute s1/s2 via 16-lane shfl reduce.
    const float4 a1 = *(const float4*)&a[c0];
    const float4 a2 = *(const float4*)&a[OUTF + c0];
    const float4 z4 = make_float4(0.f, 0.f, 0.f, 0.f);

    float p1[8], p2[8];
#pragma unroll
    for (int i = 0; i < 8; i++) {
        int r = row0 + r0 + i;
        if (r < n) {
            float4 o = make_float4(acc[i][0], acc[i][1], acc[i][2], acc[i][3]);
            *(float4*)&g_h[r * OUTF + c0] = o;
            *(float4*)&g_hp[r * OUTF + c0] = z4;
        }
        p1[i] = acc[i][0] * a1.x + acc[i][1] * a1.y + acc[i][2] * a1.z + acc[i][3] * a1.w;
        p2[i] = acc[i][0] * a2.x + acc[i][1] * a2.y + acc[i][2] * a2.z + acc[i][3] * a2.w;
    }
    // reduce across the 16 col-group lanes (lane bits 0..3)
#pragma unroll
    for (int m = 1; m < 16; m <<= 1) {
#pragma unroll
        for (int i = 0; i < 8; i++) {
            p1[i] += __shfl_xor_sync(0xffffffffu, p1[i], m);
            p2[i] += __shfl_xor_sync(0xffffffffu, p2[i], m);
        }
    }
    if (cg == 0) {
#pragma unroll
        for (int i = 0; i < 8; i++) {
            int r = row0 + r0 + i;
            if (r < n) {
                g_s1[r] = p1[i];
                g_s2[r] = p2[i];
                g_rowsum[r] = 0.f;
            }
        }
    }
}

// ---------------------------------------------------------------------------
// Kernel 2: edge scatter. One warp handles 32 edges.
// Step A: lane e computes w_e = exp(-leaky_relu(s1[src]+s2[dst])),
//         reduces rowsum[src].
// Step B: 16 rounds, 2 edges/round (half-warp each, 4 cols/lane):
//         coalesced 512B load of h[dst] + one red.global.add.v4 per lane.
// ---------------------------------------------------------------------------
__global__ __launch_bounds__(256) void k_edge(const int* __restrict__ edge,
                                              int e_total) {
    const int lane = threadIdx.x & 31;
    const int warp = (blockIdx.x * blockDim.x + threadIdx.x) >> 5;
    const int base = warp * 32;
    if (base >= e_total) return;

    int e = base + lane;
    int src = 0, dst = 0;
    float w = 0.f;
    if (e < e_total) {
        src = edge[e];
        dst = edge[e_total + e];
        float sc = g_s1[src] + g_s2[dst];
        float lr = sc > 0.f ? sc : 0.2f * sc;
        w = __expf(-lr);
        atomicAdd(&g_rowsum[src], w);
    }

    const int cnt = min(32, e_total - base);
    const int half = lane >> 4;          // 0 or 1: which edge of the pair
    const int c = (lane & 15) * 4;       // 4 cols per lane
    for (int j = 0; j < cnt; j += 2) {
        int jj = j + half;
        int s  = __shfl_sync(0xffffffffu, src, jj);
        int d  = __shfl_sync(0xffffffffu, dst, jj);
        float wj = __shfl_sync(0xffffffffu, w, jj);
        if (jj < cnt) {
            float4 hv = *(const float4*)&g_h[d * OUTF + c];
            red_add_v4(&g_hp[s * OUTF + c],
                       wj * hv.x, wj * hv.y, wj * hv.z, wj * hv.w);
        }
    }
}

// ---------------------------------------------------------------------------
// Kernel 3: out = elu(hp / rowsum)  (fast-math: slack vs 1e-3 is enormous)
// ---------------------------------------------------------------------------
__device__ __forceinline__ float elu1(float v) {
    return v > 0.f ? v : __expf(v) - 1.f;
}

__global__ __launch_bounds__(256) void k_final(float* __restrict__ out, int n) {
    int t = blockIdx.x * blockDim.x + threadIdx.x;
    if (t >= n * 16) return;
    int node = t >> 4;
    int q = t & 15;
    float rinv = __frcp_rn(g_rowsum[node]);
    float4 v = *(const float4*)&g_hp[node * OUTF + q * 4];
    float4 o;
    o.x = elu1(v.x * rinv);
    o.y = elu1(v.y * rinv);
    o.z = elu1(v.z * rinv);
    o.w = elu1(v.w * rinv);
    *(float4*)&out[node * OUTF + q * 4] = o;
}

// ---------------------------------------------------------------------------
extern "C" void kernel_launch(void* const* d_in, const int* in_sizes, int n_in,
                              void* d_out, int out_size) {
    const float* x = (const float*)d_in[0];     // [n, 128]
    const float* W = (const float*)d_in[1];     // [128, 64]
    const float* a = (const float*)d_in[2];     // [1, 128]
    const int* edge = (const int*)d_in[3];      // [2, E]
    float* out = (float*)d_out;                 // [n, 64]

    const int n = in_sizes[0] / INFT;
    const int e = in_sizes[3] / 2;

    k_gemm<<<(n + 127) / 128, 256>>>(x, W, a, n);
    k_edge<<<(e + 255) / 256, 256>>>(edge, e);
    k_final<<<(n * 16 + 255) / 256, 256>>>(out, n);
}